// round 12
// baseline (speedup 1.0000x reference)
#include <cuda_runtime.h>
#include <cstdint>

#define C_    19
#define HW_   (512*1024)
#define P_    (4*HW_)
#define TPB   256
#define TILE_PX 256                     // pixels per tile
#define NTILES  (P_/TILE_PX)            // 8192
#define TPI     (HW_/TILE_PX)           // 2048 tiles per image
#define BUFS  3
#define TILE_B  (C_*TILE_PX*4)          // 19456 bytes per tile
#define BUF_F   (C_*TILE_PX)            // 4864 floats per buffer
#define GRID_ 444                       // 3 CTAs/SM * 148 = one resident wave
#define MIN_KEPT_ 256
#define THRESH_   0.7f

// ---- device scratch (zero-initialized at load; finalize resets after each call) ----
__device__ double g_sum_wnll;
__device__ double g_sum_w;
__device__ int    g_cnt_le;
__device__ int    g_num_valid;
__device__ int    g_ov_cnt;
__device__ int    g_done;
__device__ float  g_ov_pred[P_];
__device__ float  g_ov_wnll[P_];
__device__ float  g_ov_w[P_];

// ---- mbarrier / bulk-copy PTX helpers ----
__device__ __forceinline__ unsigned smem_u32(const void* p) {
    return (unsigned)__cvta_generic_to_shared(p);
}
__device__ __forceinline__ void mbar_init(unsigned a, unsigned cnt) {
    asm volatile("mbarrier.init.shared.b64 [%0], %1;" :: "r"(a), "r"(cnt) : "memory");
}
__device__ __forceinline__ void mbar_expect_tx(unsigned a, unsigned bytes) {
    asm volatile("mbarrier.arrive.expect_tx.shared.b64 _, [%0], %1;"
                 :: "r"(a), "r"(bytes) : "memory");
}
__device__ __forceinline__ void bulk_cp(unsigned dst, const void* src,
                                        unsigned bytes, unsigned mbar) {
    asm volatile("cp.async.bulk.shared::cta.global.mbarrier::complete_tx::bytes "
                 "[%0], [%1], %2, [%3];"
                 :: "r"(dst), "l"(src), "r"(bytes), "r"(mbar) : "memory");
}
__device__ __forceinline__ void mbar_wait(unsigned a, unsigned parity) {
    unsigned done;
    asm volatile(
        "{\n\t.reg .pred p;\n\t"
        "mbarrier.try_wait.parity.acquire.cta.shared::cta.b64 p, [%1], %2, 0x989680;\n\t"
        "selp.b32 %0, 1, 0, p;\n\t}"
        : "=r"(done) : "r"(a), "r"(parity) : "memory");
    while (!done) {
        asm volatile(
            "{\n\t.reg .pred p;\n\t"
            "mbarrier.try_wait.parity.acquire.cta.shared::cta.b64 p, [%1], %2, 0x989680;\n\t"
            "selp.b32 %0, 1, 0, p;\n\t}"
            : "=r"(done) : "r"(a), "r"(parity) : "memory");
    }
}

__global__ __launch_bounds__(TPB)
void ohem_fused_kernel(const float* __restrict__ predict,
                       const int*   __restrict__ tgt,     // int32 or int64 (low words)
                       const float* __restrict__ cw,
                       float*       __restrict__ out)
{
    extern __shared__ float buf[];              // BUFS * BUF_F floats (58368B)
    __shared__ __align__(8) unsigned long long mbar_store[BUFS];
    const int tid = threadIdx.x;
    const int wid = tid >> 5, lid = tid & 31;

    // ---- init mbarriers + per-CTA target dtype detection ----
    __shared__ int s_nz;
    if (tid == 0) {
        s_nz = 0;
        for (int b = 0; b < BUFS; b++) mbar_init(smem_u32(&mbar_store[b]), 1);
    }
    __syncthreads();
    {
        const int base = blockIdx.x * TPB;      // well in-bounds for both widths
        if (tid < 128) {
            int v = __ldcs(&tgt[base + 2 * tid + 1]);
            if (v != 0 && v != -1) atomicOr(&s_nz, 1);
        }
    }
    __syncthreads();
    const int stride = s_nz ? 1 : 2;

    // ---- producer prologue: fill BUFS tiles ahead (single thread) ----
    if (tid == 0) {
#pragma unroll
        for (int i = 0; i < BUFS; i++) {
            int t = blockIdx.x + i * GRID_;
            if (t < NTILES) {
                int n  = t / TPI;
                int hw = (t % TPI) * TILE_PX;
                const float* src = predict + (size_t)n * (C_ * HW_) + hw;
                unsigned mb = smem_u32(&mbar_store[i]);
                unsigned db = smem_u32(&buf[i * BUF_F]);
                mbar_expect_tx(mb, TILE_B);
#pragma unroll
                for (int c = 0; c < C_; c++)
                    bulk_cp(db + c * (TILE_PX * 4), src + (size_t)c * HW_,
                            TILE_PX * 4, mb);
            }
        }
    }

    // ---- pipelined consume: 1 pixel per thread per tile ----
    float wnll = 0.f, wv = 0.f;
    int   cle = 0, cval = 0;

    int k = 0;
    for (int t = blockIdx.x; t < NTILES; t += GRID_, k++) {
        const int b   = k % BUFS;
        const unsigned par = (unsigned)((k / BUFS) & 1);
        mbar_wait(smem_u32(&mbar_store[b]), par);

        const int n  = t / TPI;
        const int hw = (t % TPI) * TILE_PX;
        const int p  = n * HW_ + hw + tid;
        const int lab = __ldcs(&tgt[(size_t)p * stride]);

        const float* bf = &buf[b * BUF_F + tid];
        float sum = 0.f, xl = 0.f;
#pragma unroll
        for (int c = 0; c < C_; c++) {
            float x = bf[c * TILE_PX];          // conflict-free LDS
            sum += __expf(x);
            if (lab == c) xl = x;
        }

        if (lab >= 0) {                          // valid (not IGNORE=-1)
            cval++;
            float lse = __logf(sum);
            float nll = lse - xl;                // -log p(gt)
            float pr  = __expf(-nll);            // p(gt)
            float w   = cw[lab];
            float wn  = w * nll;
            if (pr <= THRESH_) { cle++; wnll += wn; wv += w; }
            else {
                int i = atomicAdd(&g_ov_cnt, 1); // rare: pred > 0.7
                g_ov_pred[i] = pr;
                g_ov_wnll[i] = wn;
                g_ov_w[i]    = w;
                __threadfence();
            }
        }

        __syncthreads();                         // all done reading buffer b
        if (tid == 0) {
            int tn = t + BUFS * GRID_;
            if (tn < NTILES) {
                int nn  = tn / TPI;
                int nhw = (tn % TPI) * TILE_PX;
                const float* src = predict + (size_t)nn * (C_ * HW_) + nhw;
                unsigned mb = smem_u32(&mbar_store[b]);
                unsigned db = smem_u32(&buf[b * BUF_F]);
                mbar_expect_tx(mb, TILE_B);
#pragma unroll
                for (int c = 0; c < C_; c++)
                    bulk_cp(db + c * (TILE_PX * 4), src + (size_t)c * HW_,
                            TILE_PX * 4, mb);
            }
        }
    }

    // ---- once-per-CTA block reduction (8 warps) ----
#pragma unroll
    for (int o = 16; o > 0; o >>= 1) {
        wnll += __shfl_xor_sync(0xFFFFFFFFu, wnll, o);
        wv   += __shfl_xor_sync(0xFFFFFFFFu, wv,   o);
        cle  += __shfl_xor_sync(0xFFFFFFFFu, cle,  o);
        cval += __shfl_xor_sync(0xFFFFFFFFu, cval, o);
    }
    __shared__ float s_f0[8], s_f1[8];
    __shared__ int   s_i0[8], s_i1[8];
    if (lid == 0) { s_f0[wid] = wnll; s_f1[wid] = wv; s_i0[wid] = cle; s_i1[wid] = cval; }
    __syncthreads();

    __shared__ int s_last;
    if (wid == 0) {
        wnll = (lid < 8) ? s_f0[lid] : 0.f;
        wv   = (lid < 8) ? s_f1[lid] : 0.f;
        cle  = (lid < 8) ? s_i0[lid] : 0;
        cval = (lid < 8) ? s_i1[lid] : 0;
#pragma unroll
        for (int o = 4; o > 0; o >>= 1) {
            wnll += __shfl_xor_sync(0xFFFFFFFFu, wnll, o);
            wv   += __shfl_xor_sync(0xFFFFFFFFu, wv,   o);
            cle  += __shfl_xor_sync(0xFFFFFFFFu, cle,  o);
            cval += __shfl_xor_sync(0xFFFFFFFFu, cval, o);
        }
        if (lid == 0) {
            atomicAdd(&g_sum_wnll, (double)wnll);
            atomicAdd(&g_sum_w,    (double)wv);
            atomicAdd(&g_cnt_le,    cle);
            atomicAdd(&g_num_valid, cval);
            __threadfence();
            int t = atomicAdd(&g_done, 1);
            s_last = (t == GRID_ - 1);
        }
    }
    __syncthreads();
    if (!s_last) return;

    // ================= last CTA: finalize =================
    __shared__ double sd_sn, sd_sw;
    __shared__ int    si_c, si_nv, si_ov;
    if (tid == 0) {
        sd_sn = atomicAdd(&g_sum_wnll, 0.0);
        sd_sw = atomicAdd(&g_sum_w,    0.0);
        si_c  = atomicAdd(&g_cnt_le,    0);
        si_nv = atomicAdd(&g_num_valid, 0);
        si_ov = atomicAdd(&g_ov_cnt,    0);
        // reset ALL state for the next graph replay
        g_sum_wnll = 0.0; g_sum_w = 0.0;
        g_cnt_le = 0; g_num_valid = 0; g_ov_cnt = 0; g_done = 0;
    }
    __syncthreads();
    const double sn = sd_sn, sw = sd_sw;
    const int c = si_c, nv = si_nv, ov = si_ov;

    if (nv > MIN_KEPT_ && c >= MIN_KEPT_) {   // common case: threshold = 0.7
        if (tid == 0) out[0] = (float)(sn / sw);
        return;
    }

    // General case: nv <= MIN_KEPT -> keep all valid; else exact radix-select
    // of the kth-smallest pred among the overflow (>0.7) list.
    unsigned kbits = 0xFFFFFFFFu;
    __shared__ int      hist[256];
    __shared__ unsigned s_prefix;
    __shared__ int      s_rank;
    if (nv > MIN_KEPT_) {
        int rank = MIN_KEPT_ - 1 - c;           // 0-indexed rank within overflow
        unsigned prefix = 0;
        for (int shift = 24; shift >= 0; shift -= 8) {
            hist[tid] = 0;                      // TPB == 256
            __syncthreads();
            unsigned himask = (shift == 24) ? 0u : (0xFFFFFFFFu << (shift + 8));
            for (int i = tid; i < ov; i += TPB) {
                unsigned b = __float_as_uint(__ldcg(&g_ov_pred[i]));
                if ((b & himask) == prefix)
                    atomicAdd(&hist[(b >> shift) & 0xFF], 1);
            }
            __syncthreads();
            if (tid == 0) {
                int acc = 0, j = 0;
                for (; j < 256; j++) {
                    if (acc + hist[j] > rank) break;
                    acc += hist[j];
                }
                s_prefix = prefix | ((unsigned)j << shift);
                s_rank   = rank - acc;
            }
            __syncthreads();
            prefix = s_prefix;
            rank   = s_rank;
            __syncthreads();
        }
        kbits = prefix;   // pred <= kth  <=>  bits <= kbits (positive floats)
    }

    float en = 0.f, ew = 0.f;
    for (int i = tid; i < ov; i += TPB) {
        unsigned b = __float_as_uint(__ldcg(&g_ov_pred[i]));
        if (b <= kbits) { en += __ldcg(&g_ov_wnll[i]); ew += __ldcg(&g_ov_w[i]); }
    }
#pragma unroll
    for (int o = 16; o > 0; o >>= 1) {
        en += __shfl_xor_sync(0xFFFFFFFFu, en, o);
        ew += __shfl_xor_sync(0xFFFFFFFFu, ew, o);
    }
    if (lid == 0) { s_f0[wid] = en; s_f1[wid] = ew; }
    __syncthreads();
    if (tid == 0) {
        float ten = 0.f, tew = 0.f;
        for (int kk = 0; kk < 8; kk++) { ten += s_f0[kk]; tew += s_f1[kk]; }
        out[0] = (float)((sn + (double)ten) / (sw + (double)tew));
    }
}

// ---------------------------------------------------------------------------
extern "C" void kernel_launch(void* const* d_in, const int* in_sizes, int n_in,
                              void* d_out, int out_size) {
    const float* predict = (const float*)d_in[0];
    const int*   target  = (const int*)d_in[1];
    const float* cw      = (const float*)d_in[2];
    float*       out     = (float*)d_out;

    cudaFuncSetAttribute(ohem_fused_kernel,
                         cudaFuncAttributeMaxDynamicSharedMemorySize,
                         BUFS * TILE_B);
    ohem_fused_kernel<<<GRID_, TPB, BUFS * TILE_B>>>(predict, target, cw, out);
}

// round 14
// speedup vs baseline: 1.1846x; 1.1846x over previous
#include <cuda_runtime.h>
#include <cstdint>

#define C_    19
#define CRES  13                       // planes 0..12 L2 evict_last, 13..18 streamed
#define HW_   (512*1024)
#define P_    (4*HW_)
#define TPB   256
#define GRID_ 512                      // 512*256*2reps*8px == P_ exactly, one wave
#define REPS  2
#define GSTRIDE (GRID_*TPB)            // stride in 8-pixel groups
#define MIN_KEPT_ 256
#define THRESH_   0.7f

// ---- device scratch (zero-initialized at load; finalize resets after each call) ----
__device__ double g_sum_wnll;
__device__ double g_sum_w;
__device__ int    g_cnt_le;
__device__ int    g_num_valid;
__device__ int    g_ov_cnt;
__device__ int    g_done;
__device__ float  g_ov_pred[P_];
__device__ float  g_ov_wnll[P_];
__device__ float  g_ov_w[P_];

// 32B retention-biased load (the ONLY width ptxas accepts for L2::evict_last).
__device__ __forceinline__ void ld_el_f8(const float* p, float v[8]) {
    unsigned r0, r1, r2, r3, r4, r5, r6, r7;
    asm volatile("ld.global.nc.L2::evict_last.v8.b32 "
                 "{%0,%1,%2,%3,%4,%5,%6,%7}, [%8];"
                 : "=r"(r0), "=r"(r1), "=r"(r2), "=r"(r3),
                   "=r"(r4), "=r"(r5), "=r"(r6), "=r"(r7)
                 : "l"(p));
    v[0] = __uint_as_float(r0); v[1] = __uint_as_float(r1);
    v[2] = __uint_as_float(r2); v[3] = __uint_as_float(r3);
    v[4] = __uint_as_float(r4); v[5] = __uint_as_float(r5);
    v[6] = __uint_as_float(r6); v[7] = __uint_as_float(r7);
}
// streaming 32B load as two evict-first float4s
__device__ __forceinline__ void ld_cs_f8(const float* p, float v[8]) {
    float4 a = __ldcs(reinterpret_cast<const float4*>(p));
    float4 b = __ldcs(reinterpret_cast<const float4*>(p) + 1);
    v[0] = a.x; v[1] = a.y; v[2] = a.z; v[3] = a.w;
    v[4] = b.x; v[5] = b.y; v[6] = b.z; v[7] = b.w;
}
__device__ __forceinline__ void ldplane(int c, const float* p, float v[8]) {
    if (c < CRES) ld_el_f8(p, v); else ld_cs_f8(p, v);
}

__global__ __launch_bounds__(TPB, 4)
void ohem_fused_kernel(const float* __restrict__ predict,
                       const int*   __restrict__ tgt,     // int32 or int64 (low words)
                       const float* __restrict__ cw,
                       float*       __restrict__ out)
{
    const int tid = threadIdx.x;
    const int wid = tid >> 5, lid = tid & 31;

    // ---- per-CTA target dtype detection (in-bounds for both widths) ----
    __shared__ int s_nz;
    if (tid == 0) s_nz = 0;
    __syncthreads();
    {
        const int base = blockIdx.x * TPB;
        if (tid < 128) {
            int v = tgt[base + 2 * tid + 1];
            if (v != 0 && v != -1) atomicOr(&s_nz, 1);
        }
    }
    __syncthreads();
    const int stride = s_nz ? 1 : 2;

    float wnll = 0.f, wv = 0.f;
    int   cle = 0, cval = 0;

#pragma unroll
    for (int rep = 0; rep < REPS; rep++) {
        const int g  = blockIdx.x * TPB + tid + rep * GSTRIDE;
        const int p0 = g * 8;                    // 8 consecutive pixels, 32B aligned
        const int n  = p0 >> 19;                 // p / HW_
        const int hw = p0 & (HW_ - 1);
        const float* gp = predict + (size_t)n * (C_ * HW_) + hw;

        int lab[8];
#pragma unroll
        for (int j = 0; j < 8; j++) lab[j] = tgt[(size_t)(p0 + j) * stride];

        float sum[8], xl[8];
#pragma unroll
        for (int j = 0; j < 8; j++) { sum[j] = 0.f; xl[j] = 0.f; }

        // rolling depth-2 prefetch over planes, 8-wide
        float a[2][8], nxt[8];
        ldplane(0, gp, a[0]);
        ldplane(1, gp + HW_, a[1]);
#pragma unroll
        for (int c = 0; c < C_; c++) {
            if (c + 2 < C_) ldplane(c + 2, gp + (size_t)(c + 2) * HW_, nxt);
            const float* v = a[c & 1];
#pragma unroll
            for (int j = 0; j < 8; j++) {
                sum[j] += __expf(v[j]);
                if (lab[j] == c) xl[j] = v[j];
            }
            if (c + 2 < C_) {
#pragma unroll
                for (int j = 0; j < 8; j++) a[c & 1][j] = nxt[j];
            }
        }

#pragma unroll
        for (int j = 0; j < 8; j++) {
            if (lab[j] >= 0) {                    // valid (not IGNORE=-1)
                cval++;
                float lse = __logf(sum[j]);
                float nll = lse - xl[j];          // -log p(gt)
                float pr  = __expf(-nll);         // p(gt)
                float w   = cw[lab[j]];
                float wn  = w * nll;
                if (pr <= THRESH_) { cle++; wnll += wn; wv += w; }
                else {
                    int i = atomicAdd(&g_ov_cnt, 1);   // rare: pred > 0.7
                    g_ov_pred[i] = pr;
                    g_ov_wnll[i] = wn;
                    g_ov_w[i]    = w;
                    __threadfence();
                }
            }
        }
    }

    // ---- once-per-CTA block reduction (8 warps) ----
#pragma unroll
    for (int o = 16; o > 0; o >>= 1) {
        wnll += __shfl_xor_sync(0xFFFFFFFFu, wnll, o);
        wv   += __shfl_xor_sync(0xFFFFFFFFu, wv,   o);
        cle  += __shfl_xor_sync(0xFFFFFFFFu, cle,  o);
        cval += __shfl_xor_sync(0xFFFFFFFFu, cval, o);
    }
    __shared__ float s_f0[8], s_f1[8];
    __shared__ int   s_i0[8], s_i1[8];
    if (lid == 0) { s_f0[wid] = wnll; s_f1[wid] = wv; s_i0[wid] = cle; s_i1[wid] = cval; }
    __syncthreads();

    __shared__ int s_last;
    if (wid == 0) {
        wnll = (lid < 8) ? s_f0[lid] : 0.f;
        wv   = (lid < 8) ? s_f1[lid] : 0.f;
        cle  = (lid < 8) ? s_i0[lid] : 0;
        cval = (lid < 8) ? s_i1[lid] : 0;
#pragma unroll
        for (int o = 4; o > 0; o >>= 1) {
            wnll += __shfl_xor_sync(0xFFFFFFFFu, wnll, o);
            wv   += __shfl_xor_sync(0xFFFFFFFFu, wv,   o);
            cle  += __shfl_xor_sync(0xFFFFFFFFu, cle,  o);
            cval += __shfl_xor_sync(0xFFFFFFFFu, cval, o);
        }
        if (lid == 0) {
            atomicAdd(&g_sum_wnll, (double)wnll);
            atomicAdd(&g_sum_w,    (double)wv);
            atomicAdd(&g_cnt_le,    cle);
            atomicAdd(&g_num_valid, cval);
            __threadfence();
            int t = atomicAdd(&g_done, 1);
            s_last = (t == GRID_ - 1);
        }
    }
    __syncthreads();
    if (!s_last) return;

    // ================= last CTA: finalize =================
    __shared__ double sd_sn, sd_sw;
    __shared__ int    si_c, si_nv, si_ov;
    if (tid == 0) {
        sd_sn = atomicAdd(&g_sum_wnll, 0.0);
        sd_sw = atomicAdd(&g_sum_w,    0.0);
        si_c  = atomicAdd(&g_cnt_le,    0);
        si_nv = atomicAdd(&g_num_valid, 0);
        si_ov = atomicAdd(&g_ov_cnt,    0);
        // reset ALL state for the next graph replay
        g_sum_wnll = 0.0; g_sum_w = 0.0;
        g_cnt_le = 0; g_num_valid = 0; g_ov_cnt = 0; g_done = 0;
    }
    __syncthreads();
    const double sn = sd_sn, sw = sd_sw;
    const int c = si_c, nv = si_nv, ov = si_ov;

    if (nv > MIN_KEPT_ && c >= MIN_KEPT_) {   // common case: threshold = 0.7
        if (tid == 0) out[0] = (float)(sn / sw);
        return;
    }

    // General case: nv <= MIN_KEPT -> keep all valid; else exact radix-select
    // of the kth-smallest pred among the overflow (>0.7) list.
    unsigned kbits = 0xFFFFFFFFu;
    __shared__ int      hist[256];
    __shared__ unsigned s_prefix;
    __shared__ int      s_rank;
    if (nv > MIN_KEPT_) {
        int rank = MIN_KEPT_ - 1 - c;           // 0-indexed rank within overflow
        unsigned prefix = 0;
        for (int shift = 24; shift >= 0; shift -= 8) {
            hist[tid] = 0;                      // TPB == 256
            __syncthreads();
            unsigned himask = (shift == 24) ? 0u : (0xFFFFFFFFu << (shift + 8));
            for (int i = tid; i < ov; i += TPB) {
                unsigned b = __float_as_uint(__ldcg(&g_ov_pred[i]));
                if ((b & himask) == prefix)
                    atomicAdd(&hist[(b >> shift) & 0xFF], 1);
            }
            __syncthreads();
            if (tid == 0) {
                int acc = 0, j = 0;
                for (; j < 256; j++) {
                    if (acc + hist[j] > rank) break;
                    acc += hist[j];
                }
                s_prefix = prefix | ((unsigned)j << shift);
                s_rank   = rank - acc;
            }
            __syncthreads();
            prefix = s_prefix;
            rank   = s_rank;
            __syncthreads();
        }
        kbits = prefix;   // pred <= kth  <=>  bits <= kbits (positive floats)
    }

    float en = 0.f, ew = 0.f;
    for (int i = tid; i < ov; i += TPB) {
        unsigned b = __float_as_uint(__ldcg(&g_ov_pred[i]));
        if (b <= kbits) { en += __ldcg(&g_ov_wnll[i]); ew += __ldcg(&g_ov_w[i]); }
    }
#pragma unroll
    for (int o = 16; o > 0; o >>= 1) {
        en += __shfl_xor_sync(0xFFFFFFFFu, en, o);
        ew += __shfl_xor_sync(0xFFFFFFFFu, ew, o);
    }
    if (lid == 0) { s_f0[wid] = en; s_f1[wid] = ew; }
    __syncthreads();
    if (tid == 0) {
        float ten = 0.f, tew = 0.f;
        for (int k = 0; k < 8; k++) { ten += s_f0[k]; tew += s_f1[k]; }
        out[0] = (float)((sn + (double)ten) / (sw + (double)tew));
    }
}

// ---------------------------------------------------------------------------
extern "C" void kernel_launch(void* const* d_in, const int* in_sizes, int n_in,
                              void* d_out, int out_size) {
    const float* predict = (const float*)d_in[0];
    const int*   target  = (const int*)d_in[1];
    const float* cw      = (const float*)d_in[2];
    float*       out     = (float*)d_out;

    ohem_fused_kernel<<<GRID_, TPB>>>(predict, target, cw, out);
}

// round 15
// speedup vs baseline: 1.2640x; 1.0670x over previous
#include <cuda_runtime.h>
#include <cstdint>

#define C_    19
#define HW_   (512*1024)
#define P_    (4*HW_)
#define TPB   256
#define NSM   148
#define CPS   6                        // CTAs per SM (one resident wave)
#define GRID_ (NSM*CPS)                // 888 persistent CTAs
#define NGRP  (P_/4)                   // float4 pixel-groups total
#define GSTRIDE (GRID_*TPB)            // grid-stride in groups
#define MIN_KEPT_ 256
#define THRESH_   0.7f
#define PLANE4 (HW_/4)                 // float4 stride between class planes

// ---- device scratch (zero-initialized at load; finalize resets after each call) ----
__device__ double g_sum_wnll;
__device__ double g_sum_w;
__device__ int    g_cnt_le;
__device__ int    g_num_valid;
__device__ int    g_ov_cnt;
__device__ int    g_done;
__device__ float  g_ov_pred[P_];
__device__ float  g_ov_wnll[P_];
__device__ float  g_ov_w[P_];

__global__ __launch_bounds__(TPB, CPS)   // ~42-reg cap -> 6 CTAs/SM resident
void ohem_fused_kernel(const float* __restrict__ predict,
                       const int*   __restrict__ tgt,     // int32 or int64 (low words)
                       const float* __restrict__ cw,
                       float*       __restrict__ out)
{
    const int tid = threadIdx.x;
    const int wid = tid >> 5, lid = tid & 31;

    // ---- per-CTA target dtype detection (in-bounds for both widths) ----
    __shared__ int s_nz;
    if (tid == 0) s_nz = 0;
    __syncthreads();
    {
        const int base = blockIdx.x * TPB;       // < P_ for all 888 CTAs
        if (tid < 128) {
            int v = tgt[base + 2 * tid + 1];
            if (v != 0 && v != -1) atomicOr(&s_nz, 1);
        }
    }
    __syncthreads();
    const bool is64 = (s_nz == 0);

    // ---- persistent grid-stride over float4 pixel-groups ----
    float wnll = 0.f, wv = 0.f;
    int   cle = 0, cval = 0;

    for (int g = blockIdx.x * TPB + tid; g < NGRP; g += GSTRIDE) {
        const int p0 = g * 4;
        const int n  = p0 >> 19;                 // p / HW_
        const int hw = p0 & (HW_ - 1);
        const float4* base =
            reinterpret_cast<const float4*>(predict + (size_t)n * (C_ * HW_) + hw);

        // vectorized label loads: p0 % 4 == 0, so both forms are aligned.
        int lab[4];
        if (is64) {                               // int64: extract low words
            const int4* t4 = reinterpret_cast<const int4*>(tgt) + ((size_t)p0 >> 1);
            int4 a = __ldg(t4);
            int4 b = __ldg(t4 + 1);
            lab[0] = a.x; lab[1] = a.z; lab[2] = b.x; lab[3] = b.z;
        } else {                                  // int32: one 16B load
            int4 a = __ldg(reinterpret_cast<const int4*>(tgt) + (p0 >> 2));
            lab[0] = a.x; lab[1] = a.y; lab[2] = a.z; lab[3] = a.w;
        }

        float sum[4] = {0.f, 0.f, 0.f, 0.f};
        float xl[4]  = {0.f, 0.f, 0.f, 0.f};

        // rolling pipeline over classes: prefetch c+2 while processing c
        float4 v0 = __ldcs(&base[0]);
        float4 v1 = __ldcs(&base[PLANE4]);
#pragma unroll
        for (int c = 0; c < C_; c++) {
            float4 nxt;
            if (c + 2 < C_) nxt = __ldcs(&base[(size_t)(c + 2) * PLANE4]);
            sum[0] += __expf(v0.x); if (lab[0] == c) xl[0] = v0.x;
            sum[1] += __expf(v0.y); if (lab[1] == c) xl[1] = v0.y;
            sum[2] += __expf(v0.z); if (lab[2] == c) xl[2] = v0.z;
            sum[3] += __expf(v0.w); if (lab[3] == c) xl[3] = v0.w;
            v0 = v1;
            v1 = nxt;
        }

#pragma unroll
        for (int j = 0; j < 4; j++) {
            if (lab[j] >= 0) {                    // valid (not IGNORE=-1)
                cval++;
                float lse = __logf(sum[j]);
                float nll = lse - xl[j];          // -log p(gt)
                float pr  = __expf(-nll);         // p(gt)
                float w   = cw[lab[j]];
                float wn  = w * nll;
                if (pr <= THRESH_) { cle++; wnll += wn; wv += w; }
                else {
                    int i = atomicAdd(&g_ov_cnt, 1);   // rare: pred > 0.7
                    g_ov_pred[i] = pr;
                    g_ov_wnll[i] = wn;
                    g_ov_w[i]    = w;
                    __threadfence();
                }
            }
        }
    }

    // ---- once-per-CTA block reduction (8 warps) ----
#pragma unroll
    for (int o = 16; o > 0; o >>= 1) {
        wnll += __shfl_xor_sync(0xFFFFFFFFu, wnll, o);
        wv   += __shfl_xor_sync(0xFFFFFFFFu, wv,   o);
        cle  += __shfl_xor_sync(0xFFFFFFFFu, cle,  o);
        cval += __shfl_xor_sync(0xFFFFFFFFu, cval, o);
    }
    __shared__ float s_f0[8], s_f1[8];
    __shared__ int   s_i0[8], s_i1[8];
    if (lid == 0) { s_f0[wid] = wnll; s_f1[wid] = wv; s_i0[wid] = cle; s_i1[wid] = cval; }
    __syncthreads();

    __shared__ int s_last;
    if (wid == 0) {
        wnll = (lid < 8) ? s_f0[lid] : 0.f;
        wv   = (lid < 8) ? s_f1[lid] : 0.f;
        cle  = (lid < 8) ? s_i0[lid] : 0;
        cval = (lid < 8) ? s_i1[lid] : 0;
#pragma unroll
        for (int o = 4; o > 0; o >>= 1) {
            wnll += __shfl_xor_sync(0xFFFFFFFFu, wnll, o);
            wv   += __shfl_xor_sync(0xFFFFFFFFu, wv,   o);
            cle  += __shfl_xor_sync(0xFFFFFFFFu, cle,  o);
            cval += __shfl_xor_sync(0xFFFFFFFFu, cval, o);
        }
        if (lid == 0) {
            atomicAdd(&g_sum_wnll, (double)wnll);
            atomicAdd(&g_sum_w,    (double)wv);
            atomicAdd(&g_cnt_le,    cle);
            atomicAdd(&g_num_valid, cval);
            __threadfence();
            int t = atomicAdd(&g_done, 1);
            s_last = (t == GRID_ - 1);
        }
    }
    __syncthreads();
    if (!s_last) return;

    // ================= last CTA: finalize =================
    __shared__ double sd_sn, sd_sw;
    __shared__ int    si_c, si_nv, si_ov;
    if (tid == 0) {
        sd_sn = atomicAdd(&g_sum_wnll, 0.0);
        sd_sw = atomicAdd(&g_sum_w,    0.0);
        si_c  = atomicAdd(&g_cnt_le,    0);
        si_nv = atomicAdd(&g_num_valid, 0);
        si_ov = atomicAdd(&g_ov_cnt,    0);
        // reset ALL state for the next graph replay
        g_sum_wnll = 0.0; g_sum_w = 0.0;
        g_cnt_le = 0; g_num_valid = 0; g_ov_cnt = 0; g_done = 0;
    }
    __syncthreads();
    const double sn = sd_sn, sw = sd_sw;
    const int c = si_c, nv = si_nv, ov = si_ov;

    if (nv > MIN_KEPT_ && c >= MIN_KEPT_) {   // common case: threshold = 0.7
        if (tid == 0) out[0] = (float)(sn / sw);
        return;
    }

    // General case: nv <= MIN_KEPT -> keep all valid; else exact radix-select
    // of the kth-smallest pred among the overflow (>0.7) list.
    unsigned kbits = 0xFFFFFFFFu;
    __shared__ int      hist[256];
    __shared__ unsigned s_prefix;
    __shared__ int      s_rank;
    if (nv > MIN_KEPT_) {
        int rank = MIN_KEPT_ - 1 - c;           // 0-indexed rank within overflow
        unsigned prefix = 0;
        for (int shift = 24; shift >= 0; shift -= 8) {
            hist[tid] = 0;                      // TPB == 256
            __syncthreads();
            unsigned himask = (shift == 24) ? 0u : (0xFFFFFFFFu << (shift + 8));
            for (int i = tid; i < ov; i += TPB) {
                unsigned b = __float_as_uint(__ldcg(&g_ov_pred[i]));
                if ((b & himask) == prefix)
                    atomicAdd(&hist[(b >> shift) & 0xFF], 1);
            }
            __syncthreads();
            if (tid == 0) {
                int acc = 0, j = 0;
                for (; j < 256; j++) {
                    if (acc + hist[j] > rank) break;
                    acc += hist[j];
                }
                s_prefix = prefix | ((unsigned)j << shift);
                s_rank   = rank - acc;
            }
            __syncthreads();
            prefix = s_prefix;
            rank   = s_rank;
            __syncthreads();
        }
        kbits = prefix;   // pred <= kth  <=>  bits <= kbits (positive floats)
    }

    float en = 0.f, ew = 0.f;
    for (int i = tid; i < ov; i += TPB) {
        unsigned b = __float_as_uint(__ldcg(&g_ov_pred[i]));
        if (b <= kbits) { en += __ldcg(&g_ov_wnll[i]); ew += __ldcg(&g_ov_w[i]); }
    }
#pragma unroll
    for (int o = 16; o > 0; o >>= 1) {
        en += __shfl_xor_sync(0xFFFFFFFFu, en, o);
        ew += __shfl_xor_sync(0xFFFFFFFFu, ew, o);
    }
    if (lid == 0) { s_f0[wid] = en; s_f1[wid] = ew; }
    __syncthreads();
    if (tid == 0) {
        float ten = 0.f, tew = 0.f;
        for (int k = 0; k < 8; k++) { ten += s_f0[k]; tew += s_f1[k]; }
        out[0] = (float)((sn + (double)ten) / (sw + (double)tew));
    }
}

// ---------------------------------------------------------------------------
extern "C" void kernel_launch(void* const* d_in, const int* in_sizes, int n_in,
                              void* d_out, int out_size) {
    const float* predict = (const float*)d_in[0];
    const int*   target  = (const int*)d_in[1];
    const float* cw      = (const float*)d_in[2];
    float*       out     = (float*)d_out;

    ohem_fused_kernel<<<GRID_, TPB>>>(predict, target, cw, out);
}